// round 12
// baseline (speedup 1.0000x reference)
#include <cuda_runtime.h>

#define BATCH 128
#define SITES 256
#define BOND 64
#define NOUT 10
#define HALFS 128            // sites per half
#define NPAIRS 64            // site pairs per half
#define SITE_BYTES 32768     // 64*64*2 floats
#define PAIR_BYTES 65536     // 2 sites per TMA stage
#define STAGES 3             // 3 * 64KB ring = 192KB

typedef unsigned long long ull;

// Scratch (device globals — no allocation allowed)
__device__ __align__(16) float g_ct[HALFS * BOND * BOND * 2]; // right half, transposed+reversed
__device__ float g_vL[BATCH * BOND];
__device__ float g_wR[BATCH * BOND];

// ---- packed f32x2 helpers ----
static __device__ __forceinline__ ull ffma2(ull a, ull b, ull c) {
    ull d;
    asm("fma.rn.f32x2 %0, %1, %2, %3;" : "=l"(d) : "l"(a), "l"(b), "l"(c));
    return d;
}
static __device__ __forceinline__ ull fadd2(ull a, ull b) {
    ull d;
    asm("add.rn.f32x2 %0, %1, %2;" : "=l"(d) : "l"(a), "l"(b));
    return d;
}
static __device__ __forceinline__ float f2lo(ull v) {
    return __uint_as_float((unsigned)(v & 0xffffffffull));
}
static __device__ __forceinline__ float f2hi(ull v) {
    return __uint_as_float((unsigned)(v >> 32));
}
static __device__ __forceinline__ ull dup2(float v) {
    unsigned u = __float_as_uint(v);
    return ((ull)u << 32) | u;
}
static __device__ __forceinline__ unsigned smem_u32(const void* p) {
    return (unsigned)__cvta_generic_to_shared(p);
}
static __device__ __forceinline__ void team_bar(int team) {
    asm volatile("bar.sync %0, %1;" :: "r"(team + 1), "r"(128) : "memory");
}

// ---- mbarrier / bulk-copy primitives ----
static __device__ __forceinline__ void mbar_init(unsigned addr, unsigned count) {
    asm volatile("mbarrier.init.shared.b64 [%0], %1;" :: "r"(addr), "r"(count) : "memory");
}
static __device__ __forceinline__ void mbar_expect_tx(unsigned addr, unsigned bytes) {
    asm volatile("mbarrier.arrive.expect_tx.shared.b64 _, [%0], %1;"
                 :: "r"(addr), "r"(bytes) : "memory");
}
static __device__ __forceinline__ void mbar_arrive(unsigned addr) {
    asm volatile("mbarrier.arrive.shared.b64 _, [%0];" :: "r"(addr) : "memory");
}
static __device__ __forceinline__ void mbar_wait(unsigned addr, unsigned parity) {
    asm volatile(
        "{\n\t"
        ".reg .pred P;\n\t"
        "WAIT_%=:\n\t"
        "mbarrier.try_wait.parity.acquire.cta.shared::cta.b64 P, [%0], %1, 0x989680;\n\t"
        "@P bra.uni DONE_%=;\n\t"
        "bra.uni WAIT_%=;\n\t"
        "DONE_%=:\n\t"
        "}"
        :: "r"(addr), "r"(parity) : "memory");
}
static __device__ __forceinline__ void bulk_g2s(unsigned dst, const void* src,
                                                unsigned bytes, unsigned mbar) {
    asm volatile(
        "cp.async.bulk.shared::cluster.global.mbarrier::complete_tx::bytes [%0], [%1], %2, [%3];"
        :: "r"(dst), "l"(src), "r"(bytes), "r"(mbar) : "memory");
}

// ============================================================
// Kernel 0: no-op — keeps ncu's -s 5 capture window on chain_kernel.
// ============================================================
__global__ void dummy_kernel() {}

// ============================================================
// Kernel 1: repack right-half cores only.
// g_ct[t][r][2l+i] = cores[255 - t][l][r][i]  (transpose, reverse order)
// ============================================================
__global__ void __launch_bounds__(256) repack_kernel(const float* __restrict__ cores) {
    int t = blockIdx.x;            // 0..127
    int s = 255 - t;
    __shared__ float2 sh[64 * 65];
    const float2* src = (const float2*)cores + (size_t)s * 4096; // [l*64 + r] -> (c0,c1)
    float2* dst = (float2*)g_ct + (size_t)t * 4096;              // [r*64 + l]
    for (int idx = threadIdx.x; idx < 4096; idx += blockDim.x) {
        int l = idx >> 6, r = idx & 63;
        sh[r * 65 + l] = src[idx];
    }
    __syncthreads();
    for (int idx = threadIdx.x; idx < 4096; idx += blockDim.x) {
        int r = idx >> 6, l = idx & 63;
        dst[idx] = sh[r * 65 + l];
    }
}

// ============================================================
// Kernel 2: vector chains. 8 warps/block = 2 independent TEAMS of
// 4 warps; each team runs the R11 row-split recurrence on its own
// 2 chains with its own named barrier (bar.sync team+1, 128). The
// two teams land on the same 4 SMSPs -> 2 independent warps/SMSP,
// so one team's barrier/LDS stalls are filled by the other team.
// Teams share the block's 3-stage x 2-site TMA ring:
//   full[stg]  (count 1): TMA complete_tx; both teams parity-wait.
//   empty[stg] (count 2): each team releases once per pair.
// grid (32,2) = 64 blocks, 4 chains per block.
// ============================================================
__global__ void __launch_bounds__(256) chain_kernel(
    const float* __restrict__ x,      // [B][S][2]
    const float* __restrict__ cores,  // [S][l][r][2]
    const float* __restrict__ lvec,
    const float* __restrict__ rvec)
{
    extern __shared__ __align__(128) char dynsmem[];   // STAGES * 64KB
    __shared__ __align__(16) ull st[2][4][64];         // [buf][chain][j] = (v,v)
    __shared__ __align__(16) ull pp[2][4][2][64];      // [team][warp][tchain][out]
    __shared__ __align__(16) float2 sx[4][HALFS];      // per-chain x, site order
    __shared__ __align__(8) ull full_store[STAGES];
    __shared__ __align__(8) ull empty_store[STAGES];

    const int tid  = threadIdx.x;
    const int team = tid >> 7;          // 0 or 1
    const int ttid = tid & 127;         // thread id within team
    const int w    = ttid >> 5;         // warp within team (0..3)
    const int lane = tid & 31;
    const int half = blockIdx.y;
    const int fc   = ttid >> 6;         // team-chain this thread finalizes (0/1)
    const int fo   = ttid & 63;         // output this thread finalizes
    const int gfc  = 2 * team + fc;     // global chain index (0..3)

    unsigned fmb[STAGES], emb[STAGES];
    #pragma unroll
    for (int si = 0; si < STAGES; ++si) {
        fmb[si] = smem_u32(&full_store[si]);
        emb[si] = smem_u32(&empty_store[si]);
    }
    if (tid == 0) {
        #pragma unroll
        for (int si = 0; si < STAGES; ++si) {
            mbar_init(fmb[si], 1);
            mbar_init(emb[si], 2);          // one release per team per pair
        }
    }

    // Stage per-chain x values (site order t). 4 chains.
    for (int i = tid; i < 4 * HALFS; i += 256) {
        int c = i >> 7, t = i & 127;
        int batch = blockIdx.x * 4 + c;
        int s = half ? (255 - t) : t;
        sx[c][t] = *(const float2*)(x + ((size_t)batch * SITES + s) * 2);
    }
    // Init state buffer 0 with the boundary vector (all 4 chains).
    const float* bv = half ? rvec : lvec;
    st[0][gfc][fo] = dup2(bv[fo]);
    __syncthreads();

    const char* gsrc = half ? (const char*)g_ct : (const char*)cores;

    // Prime the ring (pairs 0..2).
    if (tid == 0) {
        #pragma unroll
        for (int pr = 0; pr < STAGES; ++pr) {
            mbar_expect_tx(fmb[pr], PAIR_BYTES);
            bulk_g2s(smem_u32(dynsmem + (size_t)pr * PAIR_BYTES),
                     gsrc + (size_t)pr * PAIR_BYTES, PAIR_BYTES, fmb[pr]);
        }
    }

    const int cA = 2 * team;       // this team's chains
    const int cB = 2 * team + 1;

    for (int t = 0; t < HALFS; ++t) {
        const int pair = t >> 1;
        const int stg  = pair % STAGES;

        if ((t & 1) == 0) {
            // Producer (block thread 0): refill stage that held pair-1.
            if (tid == 0 && pair >= 1 && pair + 2 < NPAIRS) {
                const int s2 = (pair + 2) % STAGES;
                mbar_wait(emb[s2], ((pair - 1) / STAGES) & 1);
                mbar_expect_tx(fmb[s2], PAIR_BYTES);
                bulk_g2s(smem_u32(dynsmem + (size_t)s2 * PAIR_BYTES),
                         gsrc + (size_t)(pair + 2) * PAIR_BYTES, PAIR_BYTES, fmb[s2]);
            }
            mbar_wait(fmb[stg], (pair / STAGES) & 1);
        }

        const int cur = t & 1;  // state read buffer; write buffer = cur^1
        const ulonglong2* tp =
            (const ulonglong2*)(dynsmem + (size_t)stg * PAIR_BYTES + (size_t)cur * SITE_BYTES)
            + lane;
        const ulonglong2* sA = (const ulonglong2*)&st[cur][cA][0];
        const ulonglong2* sB = (const ulonglong2*)&st[cur][cB][0];

        // Partial dot over rows [16w, 16w+16): lane accumulates for
        // outputs 2*lane, 2*lane+1 of both team chains.
        ull a0 = 0, a1 = 0, a2 = 0, a3 = 0;   // chain cA
        ull b0 = 0, b1 = 0, b2 = 0, b3 = 0;   // chain cB
        #pragma unroll
        for (int q = 0; q < 8; ++q) {
            const int jj = 8 * w + q;
            ulonglong2 ca = tp[(2 * jj) * 32];       // row 2jj:  (c0,c1) for o0 | o0+1
            ulonglong2 cb = tp[(2 * jj + 1) * 32];   // row 2jj+1
            ulonglong2 vA = sA[jj];                  // (v,v)@2jj | (v,v)@2jj+1
            ulonglong2 vB = sB[jj];
            a0 = ffma2(ca.x, vA.x, a0);
            a1 = ffma2(ca.y, vA.x, a1);
            a2 = ffma2(cb.x, vA.y, a2);
            a3 = ffma2(cb.y, vA.y, a3);
            b0 = ffma2(ca.x, vB.x, b0);
            b1 = ffma2(ca.y, vB.x, b1);
            b2 = ffma2(cb.x, vB.y, b2);
            b3 = ffma2(cb.y, vB.y, b3);
        }
        *(ulonglong2*)&pp[team][w][0][2 * lane] =
            make_ulonglong2(fadd2(a0, a2), fadd2(a1, a3));
        *(ulonglong2*)&pp[team][w][1][2 * lane] =
            make_ulonglong2(fadd2(b0, b2), fadd2(b1, b3));

        team_bar(team);  // partials visible; team's tile reads for site done

        // Release the stage after this team consumed its second site.
        if ((t & 1) == 1 && ttid == 0)
            mbar_arrive(emb[stg]);

        // Finalize: thread handles (gfc, fo).
        ull sum = fadd2(fadd2(pp[team][0][fc][fo], pp[team][1][fc][fo]),
                        fadd2(pp[team][2][fc][fo], pp[team][3][fc][fo]));
        const float2 xv = sx[gfc][t];
        const float vo = f2lo(st[cur][gfc][fo]);
        const float nv = fmaf(xv.x, f2lo(sum), fmaf(xv.y, f2hi(sum), vo));
        st[cur ^ 1][gfc][fo] = dup2(nv);

        team_bar(team);  // new state visible before next site's dot reads
    }

    // 128 sites -> final state in buffer 0.
    float* dst = half ? g_wR : g_vL;
    dst[(blockIdx.x * 4 + gfc) * 64 + fo] = f2lo(st[0][gfc][fo]);
}

// ============================================================
// Kernel 3: logits[b][o] = sum_{l,r} vL[l] * oc[o][l][r] * wR[r]
// ============================================================
__global__ void __launch_bounds__(64) combine_kernel(
    const float* __restrict__ oc, float* __restrict__ out)
{
    const int b = blockIdx.x;
    const int tid = threadIdx.x; // 0..63 = r
    __shared__ float vL[64], wR[64];
    __shared__ float red[2];
    vL[tid] = g_vL[b * 64 + tid];
    wR[tid] = g_wR[b * 64 + tid];
    __syncthreads();
    const float w = wR[tid];
    for (int o = 0; o < NOUT; ++o) {
        float acc = 0.f;
        const float* row = oc + (size_t)o * 4096 + tid;
        #pragma unroll 16
        for (int l = 0; l < 64; ++l)
            acc = fmaf(vL[l], row[(size_t)l * 64], acc);
        float pv = acc * w;
        #pragma unroll
        for (int off = 16; off; off >>= 1)
            pv += __shfl_down_sync(0xffffffffu, pv, off);
        if ((tid & 31) == 0) red[tid >> 5] = pv;
        __syncthreads();
        if (tid == 0) out[b * NOUT + o] = red[0] + red[1];
        __syncthreads();
    }
}

extern "C" void kernel_launch(void* const* d_in, const int* in_sizes, int n_in,
                              void* d_out, int out_size) {
    const float* input_data = (const float*)d_in[0]; // [128,256,2]
    const float* cores      = (const float*)d_in[1]; // [256,64,64,2]
    const float* out_core   = (const float*)d_in[2]; // [10,64,64]
    const float* lvec       = (const float*)d_in[3]; // [64]
    const float* rvec       = (const float*)d_in[4]; // [64]
    float* out = (float*)d_out;                      // [128,10]

    cudaFuncSetAttribute(chain_kernel,
                         cudaFuncAttributeMaxDynamicSharedMemorySize,
                         STAGES * PAIR_BYTES);

    // Two no-op launches keep ncu's skip-5 capture on chain_kernel.
    dummy_kernel<<<1, 32>>>();
    dummy_kernel<<<1, 32>>>();
    repack_kernel<<<HALFS, 256>>>(cores);
    chain_kernel<<<dim3(32, 2), 256, STAGES * PAIR_BYTES>>>(input_data, cores, lvec, rvec);
    combine_kernel<<<BATCH, 64>>>(out_core, out);
}